// round 8
// baseline (speedup 1.0000x reference)
#include <cuda_runtime.h>
#include <cstdint>

#define S_DIM 1024
#define G_DIM 10
#define F_DIM 5
#define B_DIM 8
#define C_DIM 3
#define KW (2 * F_DIM + 1)   // 11
#define PLANE (S_DIM * S_DIM)

// ---------------------------------------------------------------------------
// Single fused kernel: one block per (y, b) output row.
// Prologue (per block):
//   - stage gaussian weight (121 f) and this batch's offset grids (200 f) in smem
//   - 40 threads each compute one smoothed/scaled/clipped field value
//     (2 channels x 2 field rows ry0/ry1 x 10 cols) via the 11x11 conv
//   - 20 threads y-interpolate into rowx[10]/rowy[10]
// Main loop: 256 threads x 4 warp-contiguous pixels; bilinear field upsample
// in x, grid construction, bilinear grid_sample over 3 channels.
// ---------------------------------------------------------------------------
__global__ __launch_bounds__(256, 4)
void deform_fused_kernel(const float* __restrict__ xin,
                         const float* __restrict__ off_x,
                         const float* __restrict__ off_y,
                         const float* __restrict__ weight,
                         const void* __restrict__ max_move_ptr,
                         float* __restrict__ out) {
    const int y = blockIdx.x;
    const int b = blockIdx.y;
    const int tid = threadIdx.x;

    __shared__ float sw[KW * KW];            // 121 gaussian weights
    __shared__ float soff[2][G_DIM * G_DIM]; // this batch's offset_x / offset_y
    __shared__ float ssm[40];                // smoothed: ch*20 + rsel*10 + col
    __shared__ float rowx[G_DIM];
    __shared__ float rowy[G_DIM];

    if (tid < KW * KW) sw[tid] = weight[tid];
    if (tid < 2 * G_DIM * G_DIM) {           // 200 threads (FIX: was 128..327)
        int ch = tid / (G_DIM * G_DIM);
        int r  = tid - ch * (G_DIM * G_DIM);
        soff[ch][r] = (ch ? off_y : off_x)[b * G_DIM * G_DIM + r];
    }
    __syncthreads();

    // y-axis upsample map (block-uniform): src = max((y+0.5)*G/S - 0.5, 0)
    const float AXC = (float)G_DIM / (float)S_DIM;            // 0.009765625
    const float AXB = 0.5f * AXC - 0.5f;                      // -0.4951171875
    float fy = fmaxf(fmaf((float)y, AXC, AXB), 0.0f);
    int   ry0 = (int)fy;
    float wry = fy - (float)ry0;
    int   ry1 = min(ry0 + 1, G_DIM - 1);

    if (tid < 40) {
        // decode max_move scalar (int32 or float32)
        unsigned u = *(const unsigned*)max_move_ptr;
        int as_int = (int)u;
        float mm = (as_int >= -1000000 && as_int <= 1000000) ? (float)as_int
                                                             : __int_as_float(as_int);
        float max_offset = 2.0f * mm / (float)S_DIM;

        int col  = tid % G_DIM;
        int rsel = (tid / G_DIM) & 1;
        int ch   = tid / (2 * G_DIM);
        int i    = rsel ? ry1 : ry0;

        float acc = 0.0f;
#pragma unroll
        for (int ki = 0; ki < KW; ki++) {
            int pi = min(max(i + ki - F_DIM, 0), G_DIM - 1);
#pragma unroll
            for (int kj = 0; kj < KW; kj++) {
                int pj = min(max(col + kj - F_DIM, 0), G_DIM - 1);
                acc += soff[ch][pi * G_DIM + pj] * sw[ki * KW + kj];
            }
        }
        acc *= max_offset;
        acc = fminf(fmaxf(acc, -max_offset), max_offset);
        ssm[ch * 2 * G_DIM + rsel * G_DIM + col] = acc;
    }
    __syncthreads();

    if (tid < 2 * G_DIM) {
        int ch  = tid / G_DIM;
        int col = tid - ch * G_DIM;
        float v0 = ssm[ch * 2 * G_DIM + col];
        float v1 = ssm[ch * 2 * G_DIM + G_DIM + col];
        float v  = fmaf(wry, v1 - v0, v0);
        (ch ? rowy : rowx)[col] = v;
    }
    __syncthreads();

    const float lin_y = fmaf((float)y, 2.0f / (float)(S_DIM - 1), -1.0f);

    // center on channel 1 so plane offsets are -PLANE / 0 / +PLANE
    const float* imgc1 = xin + (size_t)b * C_DIM * PLANE + PLANE;
    float* outrow = out + ((size_t)(b * C_DIM) * S_DIM + y) * S_DIM;

#pragma unroll
    for (int k = 0; k < 4; k++) {
        const int xc = tid + 256 * k;   // warp-contiguous mapping

        // x-axis upsample map
        float fxs = fmaxf(fmaf((float)xc, AXC, AXB), 0.0f);
        int   rx0 = (int)fxs;
        float wrx = fxs - (float)rx0;
        int   rx1 = min(rx0 + 1, G_DIM - 1);

        float gx0 = rowx[rx0], gx1 = rowx[rx1];
        float gy0 = rowy[rx0], gy1 = rowy[rx1];
        float gx = fmaf(wrx, gx1 - gx0, gx0);
        float gy = fmaf(wrx, gy1 - gy0, gy0);

        float lin_x = fmaf((float)xc, 2.0f / (float)(S_DIM - 1), -1.0f);
        float grid_x = fminf(fmaxf(gx + lin_x, -1.0f), 1.0f);
        float grid_y = fminf(fmaxf(gy + lin_y, -1.0f), 1.0f);

        // ix = ((grid+1)*S - 1)/2 ; in [-0.5, 1023.5]
        float ix = fmaf(grid_x, 0.5f * (float)S_DIM, 0.5f * (float)S_DIM - 0.5f);
        float iy = fmaf(grid_y, 0.5f * (float)S_DIM, 0.5f * (float)S_DIM - 0.5f);

        float fx0 = floorf(ix), fy0 = floorf(iy);
        int x0 = (int)fx0, y0 = (int)fy0;     // in [-1, 1023]
        float wx = ix - fx0, wy = iy - fy0;

        // only two boundary cases per axis possible
        float wx0 = (x0 >= 0)         ? (1.0f - wx) : 0.0f;
        float wx1 = (x0 < S_DIM - 1)  ? wx          : 0.0f;
        float wy0 = (y0 >= 0)         ? (1.0f - wy) : 0.0f;
        float wy1 = (y0 < S_DIM - 1)  ? wy          : 0.0f;

        int cx0 = max(x0, 0);
        int cx1 = min(x0 + 1, S_DIM - 1);
        int cy0 = max(y0, 0);
        int cy1 = min(y0 + 1, S_DIM - 1);

        // int32 indices, planes addressed via immediate offsets
        int i00 = cy0 * S_DIM + cx0;
        int i01 = cy0 * S_DIM + cx1;
        int i10 = cy1 * S_DIM + cx0;
        int i11 = cy1 * S_DIM + cx1;

        float cw00 = wy0 * wx0, cw01 = wy0 * wx1;
        float cw10 = wy1 * wx0, cw11 = wy1 * wx1;

#pragma unroll
        for (int c = 0; c < C_DIM; c++) {
            const int po = (c - 1) * PLANE;
            float v = imgc1[po + i00] * cw00;
            v = fmaf(imgc1[po + i01], cw01, v);
            v = fmaf(imgc1[po + i10], cw10, v);
            v = fmaf(imgc1[po + i11], cw11, v);
            outrow[(size_t)c * PLANE + xc] = v;
        }
    }
}

extern "C" void kernel_launch(void* const* d_in, const int* in_sizes, int n_in,
                              void* d_out, int out_size) {
    const float* x        = (const float*)d_in[0];
    const float* offset_x = (const float*)d_in[1];
    const float* offset_y = (const float*)d_in[2];
    const float* weight   = (const float*)d_in[3];
    const void*  max_move = d_in[4];

    float* out = (float*)d_out;

    dim3 grid(S_DIM, B_DIM);
    deform_fused_kernel<<<grid, 256>>>(x, offset_x, offset_y, weight, max_move, out);
}